// round 7
// baseline (speedup 1.0000x reference)
#include <cuda_runtime.h>
#include <mma.h>

using namespace nvcuda;

#define NN 512
#define BB 64
#define FF 128

#define BM 128
#define BK 32
#define ALDM 40    // As row stride (pad 8) — proven layout
#define BLDM 136   // Bs row stride
#define ELD  68    // epilogue buffer row stride

// scratch (allocations forbidden -> device globals)
__device__ float g_smw[NN * NN];        // softmax(weight)
__device__ float g_d[BB * NN];          // rsqrt degree
__device__ float g_xd[BB * NN * FF];    // tf32(d_k * x[b,k,f])

__device__ __forceinline__ float4 tf32x4(float a, float b, float c, float d) {
    return make_float4(wmma::__float_to_tf32(a), wmma::__float_to_tf32(b),
                       wmma::__float_to_tf32(c), wmma::__float_to_tf32(d));
}

// ---------------------------------------------------------------------------
// Kernel 1: row softmax of weight [512,512]. Warp per row.
// ---------------------------------------------------------------------------
__global__ __launch_bounds__(256) void softmax_kernel(const float* __restrict__ w) {
    int warp = threadIdx.x >> 5;
    int lane = threadIdx.x & 31;
    int row  = blockIdx.x * 8 + warp;

    const float4* wr = (const float4*)(w + (size_t)row * NN);
    float4 v[4];
    float mx = -1e30f;
#pragma unroll
    for (int j = 0; j < 4; j++) {
        v[j] = wr[lane + 32 * j];
        mx = fmaxf(mx, fmaxf(fmaxf(v[j].x, v[j].y), fmaxf(v[j].z, v[j].w)));
    }
#pragma unroll
    for (int o = 16; o; o >>= 1) mx = fmaxf(mx, __shfl_xor_sync(0xffffffffu, mx, o));

    float s = 0.0f;
#pragma unroll
    for (int j = 0; j < 4; j++) {
        v[j].x = __expf(v[j].x - mx);
        v[j].y = __expf(v[j].y - mx);
        v[j].z = __expf(v[j].z - mx);
        v[j].w = __expf(v[j].w - mx);
        s += v[j].x + v[j].y + v[j].z + v[j].w;
    }
#pragma unroll
    for (int o = 16; o; o >>= 1) s += __shfl_xor_sync(0xffffffffu, s, o);
    float inv = 1.0f / s;

    float4* orow = (float4*)(g_smw + (size_t)row * NN);
#pragma unroll
    for (int j = 0; j < 4; j++) {
        v[j].x *= inv; v[j].y *= inv; v[j].z *= inv; v[j].w *= inv;
        orow[lane + 32 * j] = v[j];
    }
}

// ---------------------------------------------------------------------------
// Kernel 2: per (b,i): d = rsqrt(1 + sum_k sm[i,k]*mask[b,i,k]) (>0 guard),
// store g_d[b,i] and g_xd[b,i,:] = tf32(d * x[b,i,:]).
// Warp per row, 8 rows per block. grid (64, 64) x 256.
// ---------------------------------------------------------------------------
__global__ __launch_bounds__(256) void degree_xd_kernel(
    const float* __restrict__ mask, const float* __restrict__ x) {
    int warp = threadIdx.x >> 5;
    int lane = threadIdx.x & 31;
    int i = blockIdx.x * 8 + warp;
    int b = blockIdx.y;

    const float4* mr = (const float4*)(mask + ((size_t)b * NN + i) * NN);
    const float4* sr = (const float4*)(g_smw + (size_t)i * NN);
    float s = 0.0f;
#pragma unroll
    for (int j = 0; j < 4; j++) {
        float4 m4 = mr[lane + 32 * j];
        float4 s4 = sr[lane + 32 * j];
        s += m4.x * s4.x + m4.y * s4.y + m4.z * s4.z + m4.w * s4.w;
    }
#pragma unroll
    for (int o = 16; o > 0; o >>= 1) s += __shfl_xor_sync(0xffffffffu, s, o);
    // butterfly leaves total in all lanes
    float tot = s + 1.0f;  // +1 from identity
    float d = (tot > 0.0f) ? rsqrtf(tot) : 0.0f;
    if (lane == 0) g_d[b * NN + i] = d;

    const float4* xr = (const float4*)(x + ((size_t)b * NN + i) * FF);
    float4* xo = (float4*)(g_xd + ((size_t)b * NN + i) * FF);
    float4 xv = xr[lane];
    xo[lane] = tf32x4(xv.x * d, xv.y * d, xv.z * d, xv.w * d);
}

// ---------------------------------------------------------------------------
// Kernel 3: tf32 tensor-core GEMM — round-6 proven skeleton + register
// prefetch pipeline; B tile is a pure copy from precomputed g_xd.
// out[b,i,f] = d_i * sum_k (sm[i,k]*mask[b,i,k]) * xd[b,k,f] + d_i^2 * x[b,i,f]
// ---------------------------------------------------------------------------
__global__ __launch_bounds__(256, 2) void gcn_gemm_wmma(
    const float* __restrict__ x,     // [B,N,F]
    const float* __restrict__ mask,  // [B,N,N]
    float* __restrict__ out)         // [B,N,F]
{
    __shared__ __align__(128) float smem[BM * ALDM + BK * BLDM];  // 37.9 KB
    float* As = smem;                // [BM][ALDM]  A[i][k] = tf32(sm*mask)
    float* Bs = smem + BM * ALDM;    // [BK][BLDM]  B[k][f] = g_xd

    const int b  = blockIdx.y;
    const int i0 = blockIdx.x * BM;
    const int t  = threadIdx.x;
    const int warp = t >> 5;
    const int wm = (warp & 3) * 32;   // warp m offset
    const int wn = (warp >> 2) * 64;  // warp n offset

    const float* maskB = mask + (size_t)b * NN * NN;
    const float* xB    = x + (size_t)b * NN * FF;
    const float* xdB   = g_xd + (size_t)b * NN * FF;
    const float* dB    = g_d + b * NN;

    // A loader: 4 lanes per row (8 floats each), 2 passes over 128 rows
    const int a_i = t >> 2;          // 0..63 (+64)
    const int a_k = (t & 3) * 8;
    // B loader: row k = t>>5 (+8 per pass), 4 floats at (t&31)*4
    const int b_f = (t & 31) * 4;
    const int b_k = t >> 5;

    wmma::fragment<wmma::accumulator, 16, 16, 8, float> acc[2][4];
#pragma unroll
    for (int im = 0; im < 2; im++)
#pragma unroll
        for (int jn = 0; jn < 4; jn++) wmma::fill_fragment(acc[im][jn], 0.0f);

    float4 pa[2][2];  // staged A product (tf32-rounded), per pass p
    float4 pb[4];     // staged B rows (already tf32 in g_xd)

    // ---- prologue: load tile kt=0 into regs
#pragma unroll
    for (int p = 0; p < 2; p++) {
        int i = a_i + p * 64;
        const float* sp = g_smw + (size_t)(i0 + i) * NN + a_k;
        const float* mp = maskB + (size_t)(i0 + i) * NN + a_k;
        float4 s0 = *(const float4*)sp;
        float4 s1 = *(const float4*)(sp + 4);
        float4 m0 = *(const float4*)mp;
        float4 m1 = *(const float4*)(mp + 4);
        pa[p][0] = tf32x4(s0.x * m0.x, s0.y * m0.y, s0.z * m0.z, s0.w * m0.w);
        pa[p][1] = tf32x4(s1.x * m1.x, s1.y * m1.y, s1.z * m1.z, s1.w * m1.w);
    }
#pragma unroll
    for (int p = 0; p < 4; p++)
        pb[p] = *(const float4*)(xdB + (size_t)(b_k + p * 8) * FF + b_f);

    for (int kt = 0; kt < NN / BK; ++kt) {
        // ---- commit staged regs to smem
#pragma unroll
        for (int p = 0; p < 2; p++) {
            int i = a_i + p * 64;
            *(float4*)(As + i * ALDM + a_k)     = pa[p][0];
            *(float4*)(As + i * ALDM + a_k + 4) = pa[p][1];
        }
#pragma unroll
        for (int p = 0; p < 4; p++)
            *(float4*)(Bs + (b_k + p * 8) * BLDM + b_f) = pb[p];
        __syncthreads();

        // ---- prefetch next tile into regs (overlaps with MMA below)
        if (kt + 1 < NN / BK) {
            const int k0n = (kt + 1) * BK;
#pragma unroll
            for (int p = 0; p < 2; p++) {
                int i = a_i + p * 64;
                const float* sp = g_smw + (size_t)(i0 + i) * NN + k0n + a_k;
                const float* mp = maskB + (size_t)(i0 + i) * NN + k0n + a_k;
                float4 s0 = *(const float4*)sp;
                float4 s1 = *(const float4*)(sp + 4);
                float4 m0 = *(const float4*)mp;
                float4 m1 = *(const float4*)(mp + 4);
                pa[p][0] = tf32x4(s0.x * m0.x, s0.y * m0.y, s0.z * m0.z, s0.w * m0.w);
                pa[p][1] = tf32x4(s1.x * m1.x, s1.y * m1.y, s1.z * m1.z, s1.w * m1.w);
            }
#pragma unroll
            for (int p = 0; p < 4; p++)
                pb[p] = *(const float4*)(xdB + (size_t)(k0n + b_k + p * 8) * FF + b_f);
        }

        // ---- tensor-core inner product: 4 k-steps of 8 (values pre-converted)
#pragma unroll
        for (int kk = 0; kk < 4; kk++) {
            wmma::fragment<wmma::matrix_a, 16, 16, 8, wmma::precision::tf32, wmma::row_major> af[2];
            wmma::fragment<wmma::matrix_b, 16, 16, 8, wmma::precision::tf32, wmma::row_major> bf[4];
#pragma unroll
            for (int im = 0; im < 2; im++)
                wmma::load_matrix_sync(af[im], As + (wm + im * 16) * ALDM + kk * 8, ALDM);
#pragma unroll
            for (int jn = 0; jn < 4; jn++)
                wmma::load_matrix_sync(bf[jn], Bs + (kk * 8) * BLDM + wn + jn * 16, BLDM);
#pragma unroll
            for (int im = 0; im < 2; im++)
#pragma unroll
                for (int jn = 0; jn < 4; jn++)
                    wmma::mma_sync(acc[im][jn], af[im], bf[jn], acc[im][jn]);
        }
        __syncthreads();
    }

    // ---- epilogue: stage acc through smem (two n-halves), apply
    //      out = d_i * acc + d_i^2 * x[i,f] in fp32
    float* buf = smem;  // [BM][ELD], reuses As/Bs
    const int er = t >> 1;             // row 0..127
    const int ec = (t & 1) * 32;       // col half within 64
#pragma unroll
    for (int half = 0; half < 2; half++) {
        __syncthreads();
        if ((warp >> 2) == half) {
#pragma unroll
            for (int im = 0; im < 2; im++)
#pragma unroll
                for (int jn = 0; jn < 4; jn++)
                    wmma::store_matrix_sync(buf + (wm + im * 16) * ELD + jn * 16,
                                            acc[im][jn], ELD, wmma::mem_row_major);
        }
        __syncthreads();

        int gi = i0 + er;
        float di  = dB[gi];
        float di2 = di * di;
        const float* xr = xB + (size_t)gi * FF + half * 64 + ec;
        float* orow     = out + ((size_t)b * NN + gi) * FF + half * 64 + ec;
#pragma unroll
        for (int q = 0; q < 8; q++) {
            float4 v  = *(const float4*)(buf + er * ELD + ec + q * 4);
            float4 xv = *(const float4*)(xr + q * 4);
            float4 o;
            o.x = di * v.x + di2 * xv.x;
            o.y = di * v.y + di2 * xv.y;
            o.z = di * v.z + di2 * xv.z;
            o.w = di * v.w + di2 * xv.w;
            *(float4*)(orow + q * 4) = o;
        }
    }
}

// ---------------------------------------------------------------------------
extern "C" void kernel_launch(void* const* d_in, const int* in_sizes, int n_in,
                              void* d_out, int out_size) {
    const float* input  = nullptr;  // 64*512*128
    const float* mask   = nullptr;  // 64*512*512
    const float* weight = nullptr;  // 512*512
    for (int i = 0; i < n_in; i++) {
        if (in_sizes[i] == BB * NN * FF)      input  = (const float*)d_in[i];
        else if (in_sizes[i] == BB * NN * NN) mask   = (const float*)d_in[i];
        else if (in_sizes[i] == NN * NN)      weight = (const float*)d_in[i];
    }
    float* out = (float*)d_out;

    softmax_kernel<<<64, 256>>>(weight);
    degree_xd_kernel<<<dim3(64, BB), 256>>>(mask, input);
    gcn_gemm_wmma<<<dim3(NN / BM, BB), 256>>>(input, mask, out);
}

// round 10
// speedup vs baseline: 1.6781x; 1.6781x over previous
#include <cuda_runtime.h>
#include <cuda_bf16.h>
#include <mma.h>
#include <cstdint>

using namespace nvcuda;

#define NN 512
#define BB 64
#define FF 128

#define BM 128
#define BK 32
#define ALDM 40    // As row stride in bf16 (80B rows: 16B-aligned, ldmatrix conflict-free)
#define BLDM 136   // Bs row stride in bf16 (272B rows)
#define ELD  68    // epilogue fp32 buffer row stride

// scratch (allocations forbidden -> device globals)
__device__ float g_smw[NN * NN];               // softmax(weight), fp32
__device__ float g_d[BB * NN];                 // rsqrt degree
__device__ __nv_bfloat16 g_xd[BB * NN * FF];   // bf16(d_k * x[b,k,f])

__device__ __forceinline__ unsigned int bf2_as_u32(__nv_bfloat162 v) {
    unsigned int r;
    memcpy(&r, &v, 4);
    return r;
}

// ---------------------------------------------------------------------------
// Kernel 1: row softmax of weight [512,512]. Warp per row.
// ---------------------------------------------------------------------------
__global__ __launch_bounds__(128) void softmax_kernel(const float* __restrict__ w) {
    int warp = threadIdx.x >> 5;
    int lane = threadIdx.x & 31;
    int row  = blockIdx.x * 4 + warp;

    const float4* wr = (const float4*)(w + (size_t)row * NN);
    float4 v[4];
    float mx = -1e30f;
#pragma unroll
    for (int j = 0; j < 4; j++) {
        v[j] = wr[lane + 32 * j];
        mx = fmaxf(mx, fmaxf(fmaxf(v[j].x, v[j].y), fmaxf(v[j].z, v[j].w)));
    }
#pragma unroll
    for (int o = 16; o; o >>= 1) mx = fmaxf(mx, __shfl_xor_sync(0xffffffffu, mx, o));

    float s = 0.0f;
#pragma unroll
    for (int j = 0; j < 4; j++) {
        v[j].x = __expf(v[j].x - mx);
        v[j].y = __expf(v[j].y - mx);
        v[j].z = __expf(v[j].z - mx);
        v[j].w = __expf(v[j].w - mx);
        s += v[j].x + v[j].y + v[j].z + v[j].w;
    }
#pragma unroll
    for (int o = 16; o; o >>= 1) s += __shfl_xor_sync(0xffffffffu, s, o);
    float inv = 1.0f / s;

    float4* orow = (float4*)(g_smw + (size_t)row * NN);
#pragma unroll
    for (int j = 0; j < 4; j++) {
        v[j].x *= inv; v[j].y *= inv; v[j].z *= inv; v[j].w *= inv;
        orow[lane + 32 * j] = v[j];
    }
}

// ---------------------------------------------------------------------------
// Kernel 2: per (b,i): d = rsqrt(1 + sum_k sm[i,k]*mask[b,i,k]) (>0 guard),
// g_d[b,i] = d;  g_xd[b,i,:] = bf16(d * x[b,i,:]).
// Warp per row, 8 rows per block. grid (64, 64) x 256.
// ---------------------------------------------------------------------------
__global__ __launch_bounds__(256) void degree_xd_kernel(
    const float* __restrict__ mask, const float* __restrict__ x) {
    int warp = threadIdx.x >> 5;
    int lane = threadIdx.x & 31;
    int i = blockIdx.x * 8 + warp;
    int b = blockIdx.y;

    const float4* mr = (const float4*)(mask + ((size_t)b * NN + i) * NN);
    const float4* sr = (const float4*)(g_smw + (size_t)i * NN);
    float s = 0.0f;
#pragma unroll
    for (int j = 0; j < 4; j++) {
        float4 m4 = mr[lane + 32 * j];
        float4 s4 = sr[lane + 32 * j];
        s += m4.x * s4.x + m4.y * s4.y + m4.z * s4.z + m4.w * s4.w;
    }
#pragma unroll
    for (int o = 16; o > 0; o >>= 1) s += __shfl_xor_sync(0xffffffffu, s, o);
    // butterfly leaves total in all lanes
    float tot = s + 1.0f;  // +1 from identity
    float d = (tot > 0.0f) ? rsqrtf(tot) : 0.0f;
    if (lane == 0) g_d[b * NN + i] = d;

    float4 xv = *(const float4*)(x + ((size_t)b * NN + i) * FF + lane * 4);
    uint2 pk;
    pk.x = bf2_as_u32(__float22bfloat162_rn(make_float2(xv.x * d, xv.y * d)));
    pk.y = bf2_as_u32(__float22bfloat162_rn(make_float2(xv.z * d, xv.w * d)));
    *(uint2*)(g_xd + ((size_t)b * NN + i) * FF + lane * 4) = pk;
}

// ---------------------------------------------------------------------------
// Kernel 3: bf16 tensor-core GEMM (wmma m16n16k16, fp32 accum) — round-6
// proven skeleton, tiles in bf16 so fragment loads become LDSM.
// out[b,i,f] = d_i * sum_k bf16(sm[i,k]*mask[b,i,k]) * bf16(d_k*x[b,k,f])
//            + d_i^2 * x[b,i,f]   (identity term full fp32)
// ---------------------------------------------------------------------------
__global__ __launch_bounds__(256, 2) void gcn_gemm_wmma(
    const float* __restrict__ x,     // [B,N,F]
    const float* __restrict__ mask,  // [B,N,N]
    float* __restrict__ out)         // [B,N,F]
{
    // max(bf16 tiles = 128*40*2 + 32*136*2 = 18944 B, epi buf = 128*68*4 = 34816 B)
    __shared__ __align__(128) char smem[BM * ELD * 4];
    __nv_bfloat16* As = (__nv_bfloat16*)smem;                   // [BM][ALDM]
    __nv_bfloat16* Bs = (__nv_bfloat16*)(smem + BM * ALDM * 2); // [BK][BLDM]

    const int b  = blockIdx.y;
    const int i0 = blockIdx.x * BM;
    const int t  = threadIdx.x;
    const int warp = t >> 5;
    const int wm = (warp & 3) * 32;   // warp m offset
    const int wn = (warp >> 2) * 64;  // warp n offset

    const float* maskB = mask + (size_t)b * NN * NN;
    const float* xB    = x + (size_t)b * NN * FF;
    const __nv_bfloat16* xdB = g_xd + (size_t)b * NN * FF;
    const float* dB    = g_d + b * NN;

    // A loader: 4 lanes per row (8 floats each), 2 passes over 128 rows
    const int a_i = t >> 2;          // 0..63 (+64)
    const int a_k = (t & 3) * 8;
    // B loader: row k = t>>3 (0..31), 16 bf16 at (t&7)*16
    const int b_k = t >> 3;
    const int b_f = (t & 7) * 16;

    wmma::fragment<wmma::accumulator, 16, 16, 16, float> acc[2][4];
#pragma unroll
    for (int im = 0; im < 2; im++)
#pragma unroll
        for (int jn = 0; jn < 4; jn++) wmma::fill_fragment(acc[im][jn], 0.0f);

    for (int kt = 0; kt < NN / BK; ++kt) {
        const int k0 = kt * BK;

        // ---- A tile: As[i][k] = bf16(sm[i0+i][k0+k] * mask[b][i0+i][k0+k])
#pragma unroll
        for (int p = 0; p < 2; p++) {
            int i = a_i + p * 64;
            const float* sp = g_smw + (size_t)(i0 + i) * NN + k0 + a_k;
            const float* mp = maskB + (size_t)(i0 + i) * NN + k0 + a_k;
            float4 s0 = *(const float4*)sp;
            float4 s1 = *(const float4*)(sp + 4);
            float4 m0 = *(const float4*)mp;
            float4 m1 = *(const float4*)(mp + 4);
            uint4 pk;
            pk.x = bf2_as_u32(__float22bfloat162_rn(make_float2(s0.x * m0.x, s0.y * m0.y)));
            pk.y = bf2_as_u32(__float22bfloat162_rn(make_float2(s0.z * m0.z, s0.w * m0.w)));
            pk.z = bf2_as_u32(__float22bfloat162_rn(make_float2(s1.x * m1.x, s1.y * m1.y)));
            pk.w = bf2_as_u32(__float22bfloat162_rn(make_float2(s1.z * m1.z, s1.w * m1.w)));
            *(uint4*)(As + i * ALDM + a_k) = pk;
        }

        // ---- B tile: pure copy of bf16 d_k*x rows (32 bytes/thread)
        {
            const uint4* src = (const uint4*)(xdB + (size_t)(k0 + b_k) * FF + b_f);
            uint4* dst = (uint4*)(Bs + b_k * BLDM + b_f);
            dst[0] = src[0];
            dst[1] = src[1];
        }
        __syncthreads();

        // ---- tensor-core inner product: 2 k-steps of 16 (LDSM fragment loads)
#pragma unroll
        for (int kk = 0; kk < 2; kk++) {
            wmma::fragment<wmma::matrix_a, 16, 16, 16, __nv_bfloat16, wmma::row_major> af[2];
            wmma::fragment<wmma::matrix_b, 16, 16, 16, __nv_bfloat16, wmma::row_major> bf[4];
#pragma unroll
            for (int im = 0; im < 2; im++)
                wmma::load_matrix_sync(af[im], As + (wm + im * 16) * ALDM + kk * 16, ALDM);
#pragma unroll
            for (int jn = 0; jn < 4; jn++)
                wmma::load_matrix_sync(bf[jn], Bs + (kk * 16) * BLDM + wn + jn * 16, BLDM);
#pragma unroll
            for (int im = 0; im < 2; im++)
#pragma unroll
                for (int jn = 0; jn < 4; jn++)
                    wmma::mma_sync(acc[im][jn], af[im], bf[jn], acc[im][jn]);
        }
        __syncthreads();
    }

    // ---- epilogue: stage acc through smem (two n-halves), apply
    //      out = d_i * acc + d_i^2 * x[i,f] in fp32
    float* buf = (float*)smem;  // [BM][ELD], reuses tiles
    const int er = t >> 1;             // row 0..127
    const int ec = (t & 1) * 32;       // col half within 64
#pragma unroll
    for (int half = 0; half < 2; half++) {
        __syncthreads();
        if ((warp >> 2) == half) {
#pragma unroll
            for (int im = 0; im < 2; im++)
#pragma unroll
                for (int jn = 0; jn < 4; jn++)
                    wmma::store_matrix_sync(buf + (wm + im * 16) * ELD + jn * 16,
                                            acc[im][jn], ELD, wmma::mem_row_major);
        }
        __syncthreads();

        int gi = i0 + er;
        float di  = dB[gi];
        float di2 = di * di;
        const float* xr = xB + (size_t)gi * FF + half * 64 + ec;
        float* orow     = out + ((size_t)b * NN + gi) * FF + half * 64 + ec;
#pragma unroll
        for (int q = 0; q < 8; q++) {
            float4 v  = *(const float4*)(buf + er * ELD + ec + q * 4);
            float4 xv = *(const float4*)(xr + q * 4);
            float4 o;
            o.x = di * v.x + di2 * xv.x;
            o.y = di * v.y + di2 * xv.y;
            o.z = di * v.z + di2 * xv.z;
            o.w = di * v.w + di2 * xv.w;
            *(float4*)(orow + q * 4) = o;
        }
    }
}

// ---------------------------------------------------------------------------
extern "C" void kernel_launch(void* const* d_in, const int* in_sizes, int n_in,
                              void* d_out, int out_size) {
    const float* input  = nullptr;  // 64*512*128
    const float* mask   = nullptr;  // 64*512*512
    const float* weight = nullptr;  // 512*512
    for (int i = 0; i < n_in; i++) {
        if (in_sizes[i] == BB * NN * FF)      input  = (const float*)d_in[i];
        else if (in_sizes[i] == BB * NN * NN) mask   = (const float*)d_in[i];
        else if (in_sizes[i] == NN * NN)      weight = (const float*)d_in[i];
    }
    float* out = (float*)d_out;

    softmax_kernel<<<128, 128>>>(weight);
    degree_xd_kernel<<<dim3(64, BB), 256>>>(mask, input);
    gcn_gemm_wmma<<<dim3(NN / BM, BB), 256>>>(input, mask, out);
}

// round 11
// speedup vs baseline: 1.7591x; 1.0483x over previous
#include <cuda_runtime.h>
#include <cuda_bf16.h>
#include <mma.h>
#include <cstdint>

using namespace nvcuda;

#define NN 512
#define BB 64
#define FF 128

#define BM 128
#define BK 32
#define ALDM 40    // As row stride in bf16 (80B rows, 16B-aligned)
#define BLDM 136   // Bs row stride in bf16 (272B rows)
#define ELD  68    // epilogue fp32 buffer row stride
#define NKT (NN / BK)

// scratch (allocations forbidden -> device globals)
__device__ float g_smw[NN * NN];               // softmax(weight), fp32
__device__ float g_d[BB * NN];                 // rsqrt degree
__device__ __nv_bfloat16 g_xd[BB * NN * FF];   // bf16(d_k * x[b,k,f])
__device__ __nv_bfloat16 g_A[(size_t)BB * NN * NN];  // bf16(sm[i,k]*mask[b,i,k])

__device__ __forceinline__ unsigned int bf2_as_u32(__nv_bfloat162 v) {
    unsigned int r;
    memcpy(&r, &v, 4);
    return r;
}
__device__ __forceinline__ uint32_t smem_u32(const void* p) {
    uint32_t a;
    asm("{ .reg .u64 t; cvta.to.shared.u64 t, %1; cvt.u32.u64 %0, t; }" : "=r"(a) : "l"(p));
    return a;
}
__device__ __forceinline__ void cp_async16(uint32_t dst, const void* src) {
    asm volatile("cp.async.cg.shared.global [%0], [%1], 16;" :: "r"(dst), "l"(src));
}
#define CP_COMMIT() asm volatile("cp.async.commit_group;" ::: "memory")
#define CP_WAIT0()  asm volatile("cp.async.wait_group 0;" ::: "memory")

// ---------------------------------------------------------------------------
// Kernel 1: row softmax of weight [512,512]. Warp per row.
// ---------------------------------------------------------------------------
__global__ __launch_bounds__(128) void softmax_kernel(const float* __restrict__ w) {
    int warp = threadIdx.x >> 5;
    int lane = threadIdx.x & 31;
    int row  = blockIdx.x * 4 + warp;

    const float4* wr = (const float4*)(w + (size_t)row * NN);
    float4 v[4];
    float mx = -1e30f;
#pragma unroll
    for (int j = 0; j < 4; j++) {
        v[j] = wr[lane + 32 * j];
        mx = fmaxf(mx, fmaxf(fmaxf(v[j].x, v[j].y), fmaxf(v[j].z, v[j].w)));
    }
#pragma unroll
    for (int o = 16; o; o >>= 1) mx = fmaxf(mx, __shfl_xor_sync(0xffffffffu, mx, o));

    float s = 0.0f;
#pragma unroll
    for (int j = 0; j < 4; j++) {
        v[j].x = __expf(v[j].x - mx);
        v[j].y = __expf(v[j].y - mx);
        v[j].z = __expf(v[j].z - mx);
        v[j].w = __expf(v[j].w - mx);
        s += v[j].x + v[j].y + v[j].z + v[j].w;
    }
#pragma unroll
    for (int o = 16; o; o >>= 1) s += __shfl_xor_sync(0xffffffffu, s, o);
    float inv = 1.0f / s;

    float4* orow = (float4*)(g_smw + (size_t)row * NN);
#pragma unroll
    for (int j = 0; j < 4; j++) {
        v[j].x *= inv; v[j].y *= inv; v[j].z *= inv; v[j].w *= inv;
        orow[lane + 32 * j] = v[j];
    }
}

// ---------------------------------------------------------------------------
// Kernel 2: per (b,i): prod = sm[i,:]*mask[b,i,:]; g_A = bf16(prod);
// d = rsqrt(1 + sum(prod)) (>0 guard); g_d = d; g_xd[b,i,:] = bf16(d*x[b,i,:]).
// Warp per row, 8 rows per block. grid (64, 64) x 256.
// ---------------------------------------------------------------------------
__global__ __launch_bounds__(256) void degree_xd_kernel(
    const float* __restrict__ mask, const float* __restrict__ x) {
    int warp = threadIdx.x >> 5;
    int lane = threadIdx.x & 31;
    int i = blockIdx.x * 8 + warp;
    int b = blockIdx.y;

    const float4* mr = (const float4*)(mask + ((size_t)b * NN + i) * NN);
    const float4* sr = (const float4*)(g_smw + (size_t)i * NN);
    uint2* ar = (uint2*)(g_A + ((size_t)b * NN + i) * NN);
    float s = 0.0f;
#pragma unroll
    for (int j = 0; j < 4; j++) {
        float4 m4 = mr[lane + 32 * j];
        float4 s4 = sr[lane + 32 * j];
        float4 p = make_float4(m4.x * s4.x, m4.y * s4.y, m4.z * s4.z, m4.w * s4.w);
        s += p.x + p.y + p.z + p.w;
        uint2 pk;
        pk.x = bf2_as_u32(__float22bfloat162_rn(make_float2(p.x, p.y)));
        pk.y = bf2_as_u32(__float22bfloat162_rn(make_float2(p.z, p.w)));
        ar[lane + 32 * j] = pk;
    }
#pragma unroll
    for (int o = 16; o > 0; o >>= 1) s += __shfl_xor_sync(0xffffffffu, s, o);
    float tot = s + 1.0f;  // +1 from identity
    float d = (tot > 0.0f) ? rsqrtf(tot) : 0.0f;
    if (lane == 0) g_d[b * NN + i] = d;

    float4 xv = *(const float4*)(x + ((size_t)b * NN + i) * FF + lane * 4);
    uint2 pk;
    pk.x = bf2_as_u32(__float22bfloat162_rn(make_float2(xv.x * d, xv.y * d)));
    pk.y = bf2_as_u32(__float22bfloat162_rn(make_float2(xv.z * d, xv.w * d)));
    *(uint2*)(g_xd + ((size_t)b * NN + i) * FF + lane * 4) = pk;
}

// ---------------------------------------------------------------------------
// Kernel 3: bf16 wmma GEMM, cp.async double-buffered tiles (pure copies).
// out[b,i,f] = d_i * sum_k A'[b,i,k] * xd[b,k,f] + d_i^2 * x[b,i,f]
// ---------------------------------------------------------------------------
#define STAGE_ELEMS (BM * ALDM + BK * BLDM)   // 9472 bf16 = 18944 B per stage

__global__ __launch_bounds__(256, 2) void gcn_gemm_wmma(
    const float* __restrict__ x,     // [B,N,F]
    float* __restrict__ out)         // [B,N,F]
{
    // 2 stages (37888 B) >= epilogue fp32 buffer (34816 B)
    __shared__ __align__(128) char smem[2 * STAGE_ELEMS * 2];

    const int b  = blockIdx.y;
    const int i0 = blockIdx.x * BM;
    const int t  = threadIdx.x;
    const int warp = t >> 5;
    const int wm = (warp & 3) * 32;   // warp m offset
    const int wn = (warp >> 2) * 64;  // warp n offset

    const float* xB = x + (size_t)b * NN * FF;
    const __nv_bfloat16* AB  = g_A + ((size_t)b * NN + i0) * NN;
    const __nv_bfloat16* xdB = g_xd + (size_t)b * NN * FF;
    const float* dB = g_d + b * NN;

    // A loader: row a_i (+64 on pass 1), 8 bf16 (16B) at a_k
    const int a_i = t >> 2;          // 0..63
    const int a_k = (t & 3) * 8;
    // B loader: row b_k (0..31), 16 bf16 (32B) at b_f
    const int b_k = t >> 3;
    const int b_f = (t & 7) * 16;

    wmma::fragment<wmma::accumulator, 16, 16, 16, float> acc[2][4];
#pragma unroll
    for (int im = 0; im < 2; im++)
#pragma unroll
        for (int jn = 0; jn < 4; jn++) wmma::fill_fragment(acc[im][jn], 0.0f);

    const uint32_t smem_base = smem_u32(smem);

    // issue cp.asyncs for tile kt into stage s
    auto issue_tile = [&](int kt, int s) {
        const int k0 = kt * BK;
        uint32_t As_u = smem_base + (uint32_t)(s * STAGE_ELEMS * 2);
        uint32_t Bs_u = As_u + BM * ALDM * 2;
#pragma unroll
        for (int p = 0; p < 2; p++) {
            int i = a_i + p * 64;
            cp_async16(As_u + (i * ALDM + a_k) * 2, AB + (size_t)i * NN + k0 + a_k);
        }
        cp_async16(Bs_u + (b_k * BLDM + b_f) * 2,     xdB + (size_t)(k0 + b_k) * FF + b_f);
        cp_async16(Bs_u + (b_k * BLDM + b_f + 8) * 2, xdB + (size_t)(k0 + b_k) * FF + b_f + 8);
        CP_COMMIT();
    };

    issue_tile(0, 0);

    for (int kt = 0; kt < NKT; ++kt) {
        CP_WAIT0();
        __syncthreads();                 // tile kt visible to all

        if (kt + 1 < NKT) issue_tile(kt + 1, (kt + 1) & 1);  // overlaps MMA below

        const __nv_bfloat16* As = (const __nv_bfloat16*)(smem + (kt & 1) * STAGE_ELEMS * 2);
        const __nv_bfloat16* Bs = As + BM * ALDM;

#pragma unroll
        for (int kk = 0; kk < 2; kk++) {
            wmma::fragment<wmma::matrix_a, 16, 16, 16, __nv_bfloat16, wmma::row_major> af[2];
            wmma::fragment<wmma::matrix_b, 16, 16, 16, __nv_bfloat16, wmma::row_major> bf[4];
#pragma unroll
            for (int im = 0; im < 2; im++)
                wmma::load_matrix_sync(af[im], As + (wm + im * 16) * ALDM + kk * 16, ALDM);
#pragma unroll
            for (int jn = 0; jn < 4; jn++)
                wmma::load_matrix_sync(bf[jn], Bs + (kk * 16) * BLDM + wn + jn * 16, BLDM);
#pragma unroll
            for (int im = 0; im < 2; im++)
#pragma unroll
                for (int jn = 0; jn < 4; jn++)
                    wmma::mma_sync(acc[im][jn], af[im], bf[jn], acc[im][jn]);
        }
        __syncthreads();                 // all reads of stage kt&1 done before kt+2 overwrites
    }

    // ---- epilogue: stage acc through smem (two n-halves), apply
    //      out = d_i * acc + d_i^2 * x[i,f] in fp32
    float* buf = (float*)smem;  // [BM][ELD], reuses stages
    const int er = t >> 1;             // row 0..127
    const int ec = (t & 1) * 32;       // col half within 64
#pragma unroll
    for (int half = 0; half < 2; half++) {
        __syncthreads();
        if ((warp >> 2) == half) {
#pragma unroll
            for (int im = 0; im < 2; im++)
#pragma unroll
                for (int jn = 0; jn < 4; jn++)
                    wmma::store_matrix_sync(buf + (wm + im * 16) * ELD + jn * 16,
                                            acc[im][jn], ELD, wmma::mem_row_major);
        }
        __syncthreads();

        int gi = i0 + er;
        float di  = dB[gi];
        float di2 = di * di;
        const float* xr = xB + (size_t)gi * FF + half * 64 + ec;
        float* orow     = out + ((size_t)b * NN + gi) * FF + half * 64 + ec;
#pragma unroll
        for (int q = 0; q < 8; q++) {
            float4 v  = *(const float4*)(buf + er * ELD + ec + q * 4);
            float4 xv = *(const float4*)(xr + q * 4);
            float4 o;
            o.x = di * v.x + di2 * xv.x;
            o.y = di * v.y + di2 * xv.y;
            o.z = di * v.z + di2 * xv.z;
            o.w = di * v.w + di2 * xv.w;
            *(float4*)(orow + q * 4) = o;
        }
    }
}

// ---------------------------------------------------------------------------
extern "C" void kernel_launch(void* const* d_in, const int* in_sizes, int n_in,
                              void* d_out, int out_size) {
    const float* input  = nullptr;  // 64*512*128
    const float* mask   = nullptr;  // 64*512*512
    const float* weight = nullptr;  // 512*512
    for (int i = 0; i < n_in; i++) {
        if (in_sizes[i] == BB * NN * FF)      input  = (const float*)d_in[i];
        else if (in_sizes[i] == BB * NN * NN) mask   = (const float*)d_in[i];
        else if (in_sizes[i] == NN * NN)      weight = (const float*)d_in[i];
    }
    float* out = (float*)d_out;

    softmax_kernel<<<128, 128>>>(weight);
    degree_xd_kernel<<<dim3(64, BB), 256>>>(mask, input);
    gcn_gemm_wmma<<<dim3(NN / BM, BB), 256>>>(input, out);
}